// round 14
// baseline (speedup 1.0000x reference)
#include <cuda_runtime.h>
#include <cuda_bf16.h>
#include <math.h>
#include <stdint.h>

// Problem constants
#define BB   64
#define TT   256
#define DD   512
#define KK   2048
#define NN   16384   // BB*TT

// GEMM tiling (bf16 HMMA m16n8k16)
#define BM   128
#define BN   64
#define BKC  64             // bf16 elements per K-chunk (128B per row)
#define NKC  (DD / BKC)     // 8
#define APITCH_B 144        // 128B data + 16B pad (conflict-free ldmatrix)
#define DPITCH   65         // f32 per dist-tile row (conflict-free row scan)
#define STAGE_BYTES ((BM + BN) * APITCH_B)   // 192*144 = 27648
#define NSTAGE 2
#define SMEM_TOTAL (NSTAGE * STAGE_BYTES)    // 55296 (dist tile 33280 fits)

#define NTILE (KK / BN)     // 32
#define CPT   6             // candidates kept per (row, n-tile) -- lossless for top-6
#define NCAND (NTILE * CPT) // 192
#define GTOP  6             // global approx top-6 -> exact rescore

// Output layout (pytree order: loss, quantized_st [B,D,T], perplexity, encoding_indices [N,1])
#define OUT_Q_OFF    1
#define OUT_PERP_OFF (1 + NN*DD)
#define OUT_IDX_OFF  (2 + NN*DD)

// ---------------------------------------------------------------------------
// Device scratch (allocation-free per harness rules)
__device__ __align__(128) __nv_bfloat16 g_A [(size_t)NN * DD];  // 16 MB
__device__ __align__(128) __nv_bfloat16 g_Wb[(size_t)KK * DD];  //  2 MB
__device__ __align__(128) float g_Xt[(size_t)NN * DD];          // 33.5 MB
__device__ float  g_xsq[NN];
__device__ float  g_wsq[KK];
__device__ float  g_cv[(size_t)NCAND * NN];   // [c][m] layout, 12.6 MB
__device__ int    g_ci[(size_t)NCAND * NN];
__device__ int    g_c6 [(size_t)NN * GTOP];
__device__ int    g_top3[NN * 3];
__device__ int    g_counts[KK];
__device__ double g_loss_sum;

// ---------------------------------------------------------------------------
__device__ __forceinline__ uint32_t s2u(const void* p) {
    uint32_t a;
    asm("{ .reg .u64 t; cvta.to.shared.u64 t, %1; cvt.u32.u64 %0, t; }" : "=r"(a) : "l"(p));
    return a;
}

#define CP_ASYNC16(dst, src) \
    asm volatile("cp.async.cg.shared.global [%0], [%1], 16;" :: "r"(dst), "l"(src))
#define CP_COMMIT asm volatile("cp.async.commit_group;" ::: "memory")
#define CP_WAIT0  asm volatile("cp.async.wait_group 0;" ::: "memory")

// ---------------------------------------------------------------------------
__global__ void k_init() {
    int i = blockIdx.x * blockDim.x + threadIdx.x;
    if (i < KK) g_counts[i] = 0;
    if (i == 0) g_loss_sum = 0.0;
}

// ---------------------------------------------------------------------------
// xsq per row (sequential over d, coalesced along t) + wsq per codebook row.
// NUMERICS MUST STAY IDENTICAL: these values feed the exact rescore compare.
__global__ void k_prep(const float* __restrict__ x, const float* __restrict__ W) {
    if (blockIdx.x < 64) {
        int b = blockIdx.x;
        int t = threadIdx.x;
        const float* p = x + (size_t)b * DD * TT + t;
        float s = 0.f;
        #pragma unroll 8
        for (int d = 0; d < DD; d++) { float v = p[(size_t)d * TT]; s += v * v; }
        g_xsq[b * TT + t] = s;
    } else {
        int row  = (blockIdx.x - 64) * 8 + (threadIdx.x >> 5);
        int lane = threadIdx.x & 31;
        const float* p = W + (size_t)row * DD;
        float s = 0.f;
        #pragma unroll
        for (int j = lane; j < DD; j += 32) { float v = p[j]; s += v * v; }
        #pragma unroll
        for (int off = 16; off; off >>= 1) s += __shfl_down_sync(0xffffffffu, s, off);
        if (lane == 0) g_wsq[row] = s;
    }
}

// ---------------------------------------------------------------------------
__global__ void k_split_w(const float* __restrict__ W) {
    int i = blockIdx.x * 256 + threadIdx.x;
    g_Wb[i] = __float2bfloat16_rn(W[i]);
}

// ---------------------------------------------------------------------------
// Transpose x [B,D,T] -> rows [m][d]: fp32 copy (for rescore) + bf16 (for GEMM)
__global__ void k_split_x(const float* __restrict__ x) {
    __shared__ float tile[32][33];
    int b  = blockIdx.z;
    int t0 = blockIdx.y * 32;
    int d0 = blockIdx.x * 32;
    int tx = threadIdx.x, ty = threadIdx.y;  // 32 x 8

    #pragma unroll
    for (int j = 0; j < 4; j++) {
        int d = d0 + ty + 8 * j;
        tile[ty + 8 * j][tx] = x[(size_t)b * DD * TT + (size_t)d * TT + t0 + tx];
    }
    __syncthreads();
    #pragma unroll
    for (int j = 0; j < 4; j++) {
        int t = t0 + ty + 8 * j;
        size_t m = (size_t)b * TT + t;
        float v = tile[tx][ty + 8 * j];
        g_Xt[m * DD + d0 + tx] = v;
        g_A [m * DD + d0 + tx] = __float2bfloat16_rn(v);
    }
}

// ---------------------------------------------------------------------------
// insertion helpers (lexicographic (value, index); matches jax.lax.top_k order)
__device__ __forceinline__ void ins3(float v, int i,
                                     float& v0, int& i0, float& v1, int& i1,
                                     float& v2, int& i2) {
    if (v < v0 || (v == v0 && i < i0)) {
        v2 = v1; i2 = i1; v1 = v0; i1 = i0; v0 = v; i0 = i;
    } else if (v < v1 || (v == v1 && i < i1)) {
        v2 = v1; i2 = i1; v1 = v; i1 = i;
    } else if (v < v2 || (v == v2 && i < i2)) {
        v2 = v; i2 = i;
    }
}
__device__ __forceinline__ void insN(float v, int i, float* vs, int* is, int n) {
    if (v >= vs[n - 1]) return;
    int p = n - 1;
    while (p > 0 && v < vs[p - 1]) { vs[p] = vs[p - 1]; is[p] = is[p - 1]; p--; }
    vs[p] = v; is[p] = i;
}

// ---------------------------------------------------------------------------
// bf16 HMMA GEMM (approx X.Wt dot products) + fused per-tile approx top-6.
// Block 128x64, 8 warps (4m x 2n), warp tile 32x32, K-chunk 64, 2-stage
// cp.async pipeline, ONE __syncthreads per chunk.
// __launch_bounds__(256, 3): acc is only 32 regs/thread now, so 3 CTAs/SM
// (24 warps, occ 37.5%) — R13 showed the kernel latency-limited at 16 warps.
__global__ __launch_bounds__(256, 3) void k_gemm() {
    extern __shared__ char smem[];
    uint32_t sbase = s2u(smem);
    int tid = threadIdx.x, wid = tid >> 5, lane = tid & 31;
    int bx = blockIdx.x;            // n-tile 0..31
    int by = blockIdx.y;            // m-tile 0..127
    int m0 = by * BM, n0 = bx * BN;
    int wm = wid & 3, wn = wid >> 2;

    const __nv_bfloat16* Ag = g_A  + (size_t)m0 * DD;
    const __nv_bfloat16* Bg = g_Wb + (size_t)n0 * DD;

    float acc[2][4][4];
    #pragma unroll
    for (int i = 0; i < 2; i++)
        #pragma unroll
        for (int j = 0; j < 4; j++)
            #pragma unroll
            for (int r = 0; r < 4; r++) acc[i][j][r] = 0.f;

    // chunk loader: (128 A + 64 B) rows x 8 x 16B = 1536 cp.async, 6/thread
    auto load_tile = [&](int stage, int kt) {
        uint32_t sA = sbase + stage * STAGE_BYTES;
        uint32_t sB = sA + BM * APITCH_B;
        #pragma unroll
        for (int r = 0; r < 6; r++) {
            int id = tid + r * 256;
            if (id < 1024) {
                int row = id >> 3, c = id & 7;
                CP_ASYNC16(sA + row * APITCH_B + c * 16,
                           Ag + (size_t)row * DD + kt + c * 8);
            } else {
                int id2 = id - 1024;
                int row = id2 >> 3, c = id2 & 7;
                CP_ASYNC16(sB + row * APITCH_B + c * 16,
                           Bg + (size_t)row * DD + kt + c * 8);
            }
        }
    };

    auto compute = [&](int stage) {
        uint32_t sA = sbase + stage * STAGE_BYTES;
        uint32_t sB = sA + BM * APITCH_B;
        #pragma unroll
        for (int ks = 0; ks < 4; ks++) {
            uint32_t a[2][4], b[4][2];
            #pragma unroll
            for (int mi = 0; mi < 2; mi++) {
                uint32_t row = wm * 32 + mi * 16 + (lane & 15);
                uint32_t ad  = sA + row * APITCH_B + ks * 32 + ((lane >> 4) << 4);
                asm volatile("ldmatrix.sync.aligned.m8n8.x4.shared.b16 {%0,%1,%2,%3}, [%4];"
                    : "=r"(a[mi][0]), "=r"(a[mi][1]), "=r"(a[mi][2]), "=r"(a[mi][3])
                    : "r"(ad));
            }
            #pragma unroll
            for (int nj = 0; nj < 2; nj++) {
                // x4 covers two n-groups of 8 (verified lane mapping, R11-R13)
                uint32_t n  = wn * 32 + nj * 16 + ((lane >> 4) << 3) + (lane & 7);
                uint32_t bd = sB + n * APITCH_B + ks * 32 + (((lane >> 3) & 1) << 4);
                asm volatile("ldmatrix.sync.aligned.m8n8.x4.shared.b16 {%0,%1,%2,%3}, [%4];"
                    : "=r"(b[2 * nj][0]), "=r"(b[2 * nj][1]),
                      "=r"(b[2 * nj + 1][0]), "=r"(b[2 * nj + 1][1])
                    : "r"(bd));
            }
            #pragma unroll
            for (int mi = 0; mi < 2; mi++)
                #pragma unroll
                for (int ni = 0; ni < 4; ni++) {
                    asm volatile(
                        "mma.sync.aligned.m16n8k16.row.col.f32.bf16.bf16.f32 "
                        "{%0,%1,%2,%3}, {%4,%5,%6,%7}, {%8,%9}, {%0,%1,%2,%3};"
                        : "+f"(acc[mi][ni][0]), "+f"(acc[mi][ni][1]),
                          "+f"(acc[mi][ni][2]), "+f"(acc[mi][ni][3])
                        : "r"(a[mi][0]), "r"(a[mi][1]), "r"(a[mi][2]), "r"(a[mi][3]),
                          "r"(b[ni][0]), "r"(b[ni][1]));
                }
        }
    };

    load_tile(0, 0); CP_COMMIT;
    for (int c = 0; c < NKC; c++) {
        CP_WAIT0;
        __syncthreads();   // chunk c resident; all threads past compute(c-1)
        if (c + 1 < NKC) { load_tile((c + 1) & 1, (c + 1) * BKC); CP_COMMIT; }
        compute(c & 1);
    }
    __syncthreads();       // all compute done before smem reuse

    // Epilogue: dump dot products to SMEM dist tile
    float* dist = reinterpret_cast<float*>(smem);
    #pragma unroll
    for (int mi = 0; mi < 2; mi++)
        #pragma unroll
        for (int ni = 0; ni < 4; ni++) {
            int r0 = wm * 32 + mi * 16 + (lane >> 2);
            int c0 = wn * 32 + ni * 8 + 2 * (lane & 3);
            dist[r0 * DPITCH + c0]           = acc[mi][ni][0];
            dist[r0 * DPITCH + c0 + 1]       = acc[mi][ni][1];
            dist[(r0 + 8) * DPITCH + c0]     = acc[mi][ni][2];
            dist[(r0 + 8) * DPITCH + c0 + 1] = acc[mi][ni][3];
        }
    __syncthreads();

    // Approx top-6 per row: ONE thread per row scans 64 cols (conflict-free:
    // bank = (tid*65 + j) mod 32 distinct per warp). No shfl merge needed.
    if (tid < BM) {
        int r = tid, m = m0 + r;
        float vs[CPT]; int is[CPT];
        #pragma unroll
        for (int s = 0; s < CPT; s++) { vs[s] = 3.402823466e38f; is[s] = 0x7fffffff; }
        const float* dr = dist + r * DPITCH;
        #pragma unroll 4
        for (int j = 0; j < BN; j++) {
            float v = g_wsq[n0 + j] - 2.0f * dr[j];
            insN(v, n0 + j, vs, is, CPT);
        }
        #pragma unroll
        for (int s = 0; s < CPT; s++) {
            g_cv[(size_t)(bx * CPT + s) * NN + m] = vs[s];
            g_ci[(size_t)(bx * CPT + s) * NN + m] = is[s];
        }
    }
}

// ---------------------------------------------------------------------------
// Merge 32 tiles x 6 candidates -> global approx top-6 per row (coalesced)
__global__ void k_merge() {
    int m = blockIdx.x * 256 + threadIdx.x;
    float vs[GTOP]; int is[GTOP];
    #pragma unroll
    for (int s = 0; s < GTOP; s++) { vs[s] = 3.402823466e38f; is[s] = 0x7fffffff; }
    for (int c = 0; c < NCAND; c++)
        insN(g_cv[(size_t)c * NN + m], g_ci[(size_t)c * NN + m], vs, is, GTOP);
    #pragma unroll
    for (int s = 0; s < GTOP; s++) g_c6[(size_t)m * GTOP + s] = is[s];
}

// ---------------------------------------------------------------------------
// Exact fp32 rescore (identical numerics to prior passing rounds) + counts/idx
__global__ void k_rescore(const float* __restrict__ W, float* __restrict__ out) {
    int wid = threadIdx.x >> 5, lane = threadIdx.x & 31;
    int m = blockIdx.x * 8 + wid;

    const float4* xp = reinterpret_cast<const float4*>(g_Xt + (size_t)m * DD);
    float4 xv[4];
    #pragma unroll
    for (int i = 0; i < 4; i++) xv[i] = xp[lane + 32 * i];

    float xs = g_xsq[m];
    float v0 = 3.402823466e38f, v1 = v0, v2 = v0;
    int   i0 = 0x7fffffff, i1 = i0, i2 = i0;

    for (int c = 0; c < GTOP; c++) {
        int idx = g_c6[(size_t)m * GTOP + c];
        const float4* wp = reinterpret_cast<const float4*>(W + (size_t)idx * DD);
        float s = 0.f;
        #pragma unroll
        for (int i = 0; i < 4; i++) {
            float4 wv = wp[lane + 32 * i];
            s = fmaf(xv[i].x, wv.x, s);
            s = fmaf(xv[i].y, wv.y, s);
            s = fmaf(xv[i].z, wv.z, s);
            s = fmaf(xv[i].w, wv.w, s);
        }
        #pragma unroll
        for (int off = 16; off; off >>= 1) s += __shfl_down_sync(0xffffffffu, s, off);
        if (lane == 0) {
            float dist = __fadd_rn(__fadd_rn(xs, g_wsq[idx]), -2.0f * s);
            ins3(dist, idx, v0, i0, v1, i1, v2, i2);
        }
    }
    if (lane == 0) {
        g_top3[m * 3 + 0] = i0;
        g_top3[m * 3 + 1] = i1;
        g_top3[m * 3 + 2] = i2;
        atomicAdd(&g_counts[i0], 1);
        atomicAdd(&g_counts[i1], 1);
        atomicAdd(&g_counts[i2], 1);
        out[OUT_IDX_OFF + m] = (float)i2;
    }
}

// ---------------------------------------------------------------------------
// Fused quantize + transpose + loss: gathers W rows directly (L2/L1-resident),
// writes out[B,D,T] coalesced. Same value math/order as reference.
__global__ void k_out(const float* __restrict__ x, const float* __restrict__ W,
                      float* __restrict__ out) {
    __shared__ double red[8];
    int b  = blockIdx.z;
    int t0 = blockIdx.y * 32;
    int d0 = blockIdx.x * 32;
    int tx = threadIdx.x, ty = threadIdx.y;   // 32 x 8

    int m = b * TT + t0 + tx;
    int j0 = g_top3[m * 3 + 0];
    int j1 = g_top3[m * 3 + 1];
    int j2 = g_top3[m * 3 + 2];
    const float* w0 = W + (size_t)j0 * DD;
    const float* w1 = W + (size_t)j1 * DD;
    const float* w2 = W + (size_t)j2 * DD;

    float lsum = 0.f;
    #pragma unroll
    for (int i = 0; i < 4; i++) {
        int d = d0 + ty + 8 * i;
        float q = ((w0[d] + w1[d]) + w2[d]) / 3.0f;
        size_t off = (size_t)b * DD * TT + (size_t)d * TT + t0 + tx;
        float xv = x[off];
        out[OUT_Q_OFF + off] = q;
        float df = q - xv;
        lsum += df * df;
    }
    #pragma unroll
    for (int off = 16; off; off >>= 1)
        lsum += __shfl_down_sync(0xffffffffu, lsum, off);
    if (tx == 0) red[ty] = (double)lsum;
    __syncthreads();
    if (tx == 0 && ty == 0) {
        double s = 0.0;
        #pragma unroll
        for (int i = 0; i < 8; i++) s += red[i];
        atomicAdd(&g_loss_sum, s);
    }
}

// ---------------------------------------------------------------------------
__global__ void k_final(float* __restrict__ out) {
    __shared__ float red[256];
    int tid = threadIdx.x;
    float local = 0.f;
    for (int k = tid; k < KK; k += 256) {
        float p = (float)g_counts[k] / 16384.0f;
        local += p * logf(p + 1e-10f);
    }
    red[tid] = local;
    __syncthreads();
    #pragma unroll
    for (int s = 128; s; s >>= 1) {
        if (tid < s) red[tid] += red[tid + s];
        __syncthreads();
    }
    if (tid == 0) {
        out[OUT_PERP_OFF] = expf(-red[0]);
        float m = (float)(g_loss_sum / (double)((size_t)NN * DD));
        out[0] = m + 0.25f * m;
    }
}

// ---------------------------------------------------------------------------
extern "C" void kernel_launch(void* const* d_in, const int* in_sizes, int n_in,
                              void* d_out, int out_size) {
    const float* x = (const float*)d_in[0];
    const float* W = (const float*)d_in[1];
    if (n_in >= 2 && in_sizes[0] == KK * DD && in_sizes[1] == BB * DD * TT) {
        const float* tmp = x; x = W; W = tmp;
    }
    float* out = (float*)d_out;
    (void)out_size;

    cudaFuncSetAttribute(k_gemm, cudaFuncAttributeMaxDynamicSharedMemorySize,
                         SMEM_TOTAL);

    // k_gemm stays at launch index 3 (ncu profiles launch #3).
    k_prep   <<<320, 256>>>(x, W);
    k_split_w<<<(KK * DD) / 256, 256>>>(W);
    k_split_x<<<dim3(16, 8, 64), dim3(32, 8)>>>(x);
    k_gemm   <<<dim3(KK / BN, NN / BM), 256, SMEM_TOTAL>>>();
    k_init   <<<8, 256>>>();
    k_merge  <<<64, 256>>>();
    k_rescore<<<2048, 256>>>(W, out);
    k_out    <<<dim3(16, 8, 64), dim3(32, 8)>>>(x, W, out);
    k_final  <<<1, 256>>>(out);
}

// round 15
// speedup vs baseline: 1.3200x; 1.3200x over previous
#include <cuda_runtime.h>
#include <cuda_bf16.h>
#include <math.h>
#include <stdint.h>

// Problem constants
#define BB   64
#define TT   256
#define DD   512
#define KK   2048
#define NN   16384   // BB*TT

// GEMM tiling (bf16 HMMA m16n8k16) — R13 proven optimum
#define BM   128
#define BN   128
#define BKC  64             // bf16 elements per K-chunk (128B per row)
#define NKC  (DD / BKC)     // 8
#define APITCH_B 144        // 128B data + 16B pad (conflict-free ldmatrix)
#define DPITCH   129        // f32 per dist-tile row
#define STAGE_BYTES ((BM + BN) * APITCH_B)   // 256*144 = 36864
#define NSTAGE 2
#define SMEM_TOTAL (NSTAGE * STAGE_BYTES)    // 73728 (dist tile 66048 fits inside)

#define NTILE (KK / BN)     // 16
#define CPT   4             // candidates kept per (row, n-tile)
#define NCAND (NTILE * CPT) // 64
#define GTOP  6             // global approx top-6 -> exact rescore

// Output layout (pytree order: loss, quantized_st [B,D,T], perplexity, encoding_indices [N,1])
#define OUT_Q_OFF    1
#define OUT_PERP_OFF (1 + NN*DD)
#define OUT_IDX_OFF  (2 + NN*DD)

// ---------------------------------------------------------------------------
// Device scratch (allocation-free per harness rules)
__device__ __align__(128) __nv_bfloat16 g_A [(size_t)NN * DD];  // 16 MB
__device__ __align__(128) __nv_bfloat16 g_Wb[(size_t)KK * DD];  //  2 MB
__device__ __align__(128) float g_Xt[(size_t)NN * DD];          // 33.5 MB
__device__ float  g_xsq[NN];
__device__ float  g_wsq[KK];
__device__ float  g_cv[(size_t)NCAND * NN];   // [c][m] layout
__device__ int    g_ci[(size_t)NCAND * NN];
__device__ int    g_c6 [(size_t)NN * GTOP];
__device__ int    g_top3[NN * 3];
__device__ int    g_counts[KK];
__device__ double g_loss_sum;

// ---------------------------------------------------------------------------
__device__ __forceinline__ uint32_t s2u(const void* p) {
    uint32_t a;
    asm("{ .reg .u64 t; cvta.to.shared.u64 t, %1; cvt.u32.u64 %0, t; }" : "=r"(a) : "l"(p));
    return a;
}

#define CP_ASYNC16(dst, src) \
    asm volatile("cp.async.cg.shared.global [%0], [%1], 16;" :: "r"(dst), "l"(src))
#define CP_COMMIT asm volatile("cp.async.commit_group;" ::: "memory")
#define CP_WAIT0  asm volatile("cp.async.wait_group 0;" ::: "memory")

// ---------------------------------------------------------------------------
// xsq per row (sequential over d, coalesced along t) + wsq per codebook row.
// NUMERICS MUST STAY IDENTICAL: these values feed the exact rescore compare.
__global__ void k_prep(const float* __restrict__ x, const float* __restrict__ W) {
    if (blockIdx.x < 64) {
        int b = blockIdx.x;
        int t = threadIdx.x;
        const float* p = x + (size_t)b * DD * TT + t;
        float s = 0.f;
        #pragma unroll 8
        for (int d = 0; d < DD; d++) { float v = p[(size_t)d * TT]; s += v * v; }
        g_xsq[b * TT + t] = s;
    } else {
        int row  = (blockIdx.x - 64) * 8 + (threadIdx.x >> 5);
        int lane = threadIdx.x & 31;
        const float* p = W + (size_t)row * DD;
        float s = 0.f;
        #pragma unroll
        for (int j = lane; j < DD; j += 32) { float v = p[j]; s += v * v; }
        #pragma unroll
        for (int off = 16; off; off >>= 1) s += __shfl_down_sync(0xffffffffu, s, off);
        if (lane == 0) g_wsq[row] = s;
    }
}

// ---------------------------------------------------------------------------
// W -> bf16, fused with scratch init (counts/loss) — saves the k_init launch.
__global__ void k_split_w(const float* __restrict__ W) {
    int i = blockIdx.x * 256 + threadIdx.x;
    g_Wb[i] = __float2bfloat16_rn(W[i]);
    if (i < KK) g_counts[i] = 0;
    if (i == 0) g_loss_sum = 0.0;
}

// ---------------------------------------------------------------------------
// Transpose x [B,D,T] -> rows [m][d]: fp32 copy (for rescore) + bf16 (for GEMM)
__global__ void k_split_x(const float* __restrict__ x) {
    __shared__ float tile[32][33];
    int b  = blockIdx.z;
    int t0 = blockIdx.y * 32;
    int d0 = blockIdx.x * 32;
    int tx = threadIdx.x, ty = threadIdx.y;  // 32 x 8

    #pragma unroll
    for (int j = 0; j < 4; j++) {
        int d = d0 + ty + 8 * j;
        tile[ty + 8 * j][tx] = x[(size_t)b * DD * TT + (size_t)d * TT + t0 + tx];
    }
    __syncthreads();
    #pragma unroll
    for (int j = 0; j < 4; j++) {
        int t = t0 + ty + 8 * j;
        size_t m = (size_t)b * TT + t;
        float v = tile[tx][ty + 8 * j];
        g_Xt[m * DD + d0 + tx] = v;
        g_A [m * DD + d0 + tx] = __float2bfloat16_rn(v);
    }
}

// ---------------------------------------------------------------------------
// insertion helpers (lexicographic (value, index); matches jax.lax.top_k order)
__device__ __forceinline__ void ins3(float v, int i,
                                     float& v0, int& i0, float& v1, int& i1,
                                     float& v2, int& i2) {
    if (v < v0 || (v == v0 && i < i0)) {
        v2 = v1; i2 = i1; v1 = v0; i1 = i0; v0 = v; i0 = i;
    } else if (v < v1 || (v == v1 && i < i1)) {
        v2 = v1; i2 = i1; v1 = v; i1 = i;
    } else if (v < v2 || (v == v2 && i < i2)) {
        v2 = v; i2 = i;
    }
}
__device__ __forceinline__ void insN(float v, int i, float* vs, int* is, int n) {
    if (v >= vs[n - 1]) return;
    int p = n - 1;
    while (p > 0 && v < vs[p - 1]) { vs[p] = vs[p - 1]; is[p] = is[p - 1]; p--; }
    vs[p] = v; is[p] = i;
}

// ---------------------------------------------------------------------------
// bf16 HMMA GEMM (approx X.Wt dot products) + fused per-tile approx top-4.
// Block 128x128, 8 warps (2m x 4n), warp tile 64x32, K-chunk 64, 2-stage
// cp.async pipeline, ONE __syncthreads per chunk. x4 ldmatrix for A and B.
// __launch_bounds__(256, 2): 2 CTAs/SM — RF-bound maximum (R13/R14 evidence:
// 64 acc regs/thread caps threads at ~595/SM; smem residency limit <166KB
// blocks any 3-CTA or 3-stage variant).
__global__ __launch_bounds__(256, 2) void k_gemm() {
    extern __shared__ char smem[];
    uint32_t sbase = s2u(smem);
    int tid = threadIdx.x, wid = tid >> 5, lane = tid & 31;
    int bx = blockIdx.x;            // n-tile 0..15
    int by = blockIdx.y;            // m-tile 0..127
    int m0 = by * BM, n0 = bx * BN;
    int wm = wid & 1, wn = wid >> 1;

    const __nv_bfloat16* Ag = g_A  + (size_t)m0 * DD;
    const __nv_bfloat16* Bg = g_Wb + (size_t)n0 * DD;

    float acc[4][4][4];
    #pragma unroll
    for (int i = 0; i < 4; i++)
        #pragma unroll
        for (int j = 0; j < 4; j++)
            #pragma unroll
            for (int r = 0; r < 4; r++) acc[i][j][r] = 0.f;

    // chunk loader: (128 A + 128 B) rows x 8 x 16B = 2048 cp.async, 8/thread
    auto load_tile = [&](int stage, int kt) {
        uint32_t sA = sbase + stage * STAGE_BYTES;
        uint32_t sB = sA + BM * APITCH_B;
        #pragma unroll
        for (int r = 0; r < 8; r++) {
            int id  = tid + r * 256;
            int row = (id >> 3) & 127;
            int c   = id & 7;
            if (id < 1024)
                CP_ASYNC16(sA + row * APITCH_B + c * 16,
                           Ag + (size_t)row * DD + kt + c * 8);
            else
                CP_ASYNC16(sB + row * APITCH_B + c * 16,
                           Bg + (size_t)row * DD + kt + c * 8);
        }
    };

    auto compute = [&](int stage) {
        uint32_t sA = sbase + stage * STAGE_BYTES;
        uint32_t sB = sA + BM * APITCH_B;
        #pragma unroll
        for (int ks = 0; ks < 4; ks++) {
            uint32_t a[4][4], b[4][2];
            #pragma unroll
            for (int mi = 0; mi < 4; mi++) {
                uint32_t row = wm * 64 + mi * 16 + (lane & 15);
                uint32_t ad  = sA + row * APITCH_B + ks * 32 + ((lane >> 4) << 4);
                asm volatile("ldmatrix.sync.aligned.m8n8.x4.shared.b16 {%0,%1,%2,%3}, [%4];"
                    : "=r"(a[mi][0]), "=r"(a[mi][1]), "=r"(a[mi][2]), "=r"(a[mi][3])
                    : "r"(ad));
            }
            #pragma unroll
            for (int nj = 0; nj < 2; nj++) {
                // x4 covers two n-groups of 8 (verified lane mapping, R11-R13)
                uint32_t n  = wn * 32 + nj * 16 + ((lane >> 4) << 3) + (lane & 7);
                uint32_t bd = sB + n * APITCH_B + ks * 32 + (((lane >> 3) & 1) << 4);
                asm volatile("ldmatrix.sync.aligned.m8n8.x4.shared.b16 {%0,%1,%2,%3}, [%4];"
                    : "=r"(b[2 * nj][0]), "=r"(b[2 * nj][1]),
                      "=r"(b[2 * nj + 1][0]), "=r"(b[2 * nj + 1][1])
                    : "r"(bd));
            }
            #pragma unroll
            for (int mi = 0; mi < 4; mi++)
                #pragma unroll
                for (int ni = 0; ni < 4; ni++) {
                    asm volatile(
                        "mma.sync.aligned.m16n8k16.row.col.f32.bf16.bf16.f32 "
                        "{%0,%1,%2,%3}, {%4,%5,%6,%7}, {%8,%9}, {%0,%1,%2,%3};"
                        : "+f"(acc[mi][ni][0]), "+f"(acc[mi][ni][1]),
                          "+f"(acc[mi][ni][2]), "+f"(acc[mi][ni][3])
                        : "r"(a[mi][0]), "r"(a[mi][1]), "r"(a[mi][2]), "r"(a[mi][3]),
                          "r"(b[ni][0]), "r"(b[ni][1]));
                }
        }
    };

    load_tile(0, 0); CP_COMMIT;
    for (int c = 0; c < NKC; c++) {
        CP_WAIT0;
        __syncthreads();   // chunk c resident; all threads past compute(c-1)
        if (c + 1 < NKC) { load_tile((c + 1) & 1, (c + 1) * BKC); CP_COMMIT; }
        compute(c & 1);
    }
    __syncthreads();       // all compute done before smem reuse

    // Epilogue: dump dot products to SMEM dist tile
    float* dist = reinterpret_cast<float*>(smem);
    #pragma unroll
    for (int mi = 0; mi < 4; mi++)
        #pragma unroll
        for (int ni = 0; ni < 4; ni++) {
            int r0 = wm * 64 + mi * 16 + (lane >> 2);
            int c0 = wn * 32 + ni * 8 + 2 * (lane & 3);
            dist[r0 * DPITCH + c0]           = acc[mi][ni][0];
            dist[r0 * DPITCH + c0 + 1]       = acc[mi][ni][1];
            dist[(r0 + 8) * DPITCH + c0]     = acc[mi][ni][2];
            dist[(r0 + 8) * DPITCH + c0 + 1] = acc[mi][ni][3];
        }
    __syncthreads();

    // Approx top-4 per row: 2 threads/row scan 64 cols each, shfl pair-merge.
    // Snapshot (ov/oi) BEFORE merging — insN mutates vs/is (R10 lesson).
    {
        int r = tid >> 1, h = tid & 1, m = m0 + r;
        float vs[CPT]; int is[CPT];
        #pragma unroll
        for (int s = 0; s < CPT; s++) { vs[s] = 3.402823466e38f; is[s] = 0x7fffffff; }
        const float* dr = dist + r * DPITCH + h * 64;
        int nb = n0 + h * 64;
        #pragma unroll 4
        for (int j = 0; j < 64; j++) {
            float v = g_wsq[nb + j] - 2.0f * dr[j];
            insN(v, nb + j, vs, is, CPT);
        }
        float ov[CPT]; int oi[CPT];
        #pragma unroll
        for (int s = 0; s < CPT; s++) { ov[s] = vs[s]; oi[s] = is[s]; }
        #pragma unroll
        for (int s = 0; s < CPT; s++) {
            float pv = __shfl_xor_sync(0xffffffffu, ov[s], 1);
            int   pi = __shfl_xor_sync(0xffffffffu, oi[s], 1);
            insN(pv, pi, vs, is, CPT);
        }
        if (h == 0) {
            #pragma unroll
            for (int s = 0; s < CPT; s++) {
                g_cv[(size_t)(bx * CPT + s) * NN + m] = vs[s];
                g_ci[(size_t)(bx * CPT + s) * NN + m] = is[s];
            }
        }
    }
}

// ---------------------------------------------------------------------------
// Merge 16 tiles x 4 candidates -> global approx top-6 per row (coalesced)
__global__ void k_merge() {
    int m = blockIdx.x * 256 + threadIdx.x;
    float vs[GTOP]; int is[GTOP];
    #pragma unroll
    for (int s = 0; s < GTOP; s++) { vs[s] = 3.402823466e38f; is[s] = 0x7fffffff; }
    for (int c = 0; c < NCAND; c++)
        insN(g_cv[(size_t)c * NN + m], g_ci[(size_t)c * NN + m], vs, is, GTOP);
    #pragma unroll
    for (int s = 0; s < GTOP; s++) g_c6[(size_t)m * GTOP + s] = is[s];
}

// ---------------------------------------------------------------------------
// Exact fp32 rescore (identical numerics to prior passing rounds) + counts/idx
__global__ void k_rescore(const float* __restrict__ W, float* __restrict__ out) {
    int wid = threadIdx.x >> 5, lane = threadIdx.x & 31;
    int m = blockIdx.x * 8 + wid;

    const float4* xp = reinterpret_cast<const float4*>(g_Xt + (size_t)m * DD);
    float4 xv[4];
    #pragma unroll
    for (int i = 0; i < 4; i++) xv[i] = xp[lane + 32 * i];

    float xs = g_xsq[m];
    float v0 = 3.402823466e38f, v1 = v0, v2 = v0;
    int   i0 = 0x7fffffff, i1 = i0, i2 = i0;

    for (int c = 0; c < GTOP; c++) {
        int idx = g_c6[(size_t)m * GTOP + c];
        const float4* wp = reinterpret_cast<const float4*>(W + (size_t)idx * DD);
        float s = 0.f;
        #pragma unroll
        for (int i = 0; i < 4; i++) {
            float4 wv = wp[lane + 32 * i];
            s = fmaf(xv[i].x, wv.x, s);
            s = fmaf(xv[i].y, wv.y, s);
            s = fmaf(xv[i].z, wv.z, s);
            s = fmaf(xv[i].w, wv.w, s);
        }
        #pragma unroll
        for (int off = 16; off; off >>= 1) s += __shfl_down_sync(0xffffffffu, s, off);
        if (lane == 0) {
            float dist = __fadd_rn(__fadd_rn(xs, g_wsq[idx]), -2.0f * s);
            ins3(dist, idx, v0, i0, v1, i1, v2, i2);
        }
    }
    if (lane == 0) {
        g_top3[m * 3 + 0] = i0;
        g_top3[m * 3 + 1] = i1;
        g_top3[m * 3 + 2] = i2;
        atomicAdd(&g_counts[i0], 1);
        atomicAdd(&g_counts[i1], 1);
        atomicAdd(&g_counts[i2], 1);
        out[OUT_IDX_OFF + m] = (float)i2;
    }
}

// ---------------------------------------------------------------------------
// Fused quantize + transpose + loss: gathers W rows directly (L2/L1-resident),
// writes out[B,D,T] coalesced. Same value math/order as reference.
__global__ void k_out(const float* __restrict__ x, const float* __restrict__ W,
                      float* __restrict__ out) {
    __shared__ double red[8];
    int b  = blockIdx.z;
    int t0 = blockIdx.y * 32;
    int d0 = blockIdx.x * 32;
    int tx = threadIdx.x, ty = threadIdx.y;   // 32 x 8

    int m = b * TT + t0 + tx;
    int j0 = g_top3[m * 3 + 0];
    int j1 = g_top3[m * 3 + 1];
    int j2 = g_top3[m * 3 + 2];
    const float* w0 = W + (size_t)j0 * DD;
    const float* w1 = W + (size_t)j1 * DD;
    const float* w2 = W + (size_t)j2 * DD;

    float lsum = 0.f;
    #pragma unroll
    for (int i = 0; i < 4; i++) {
        int d = d0 + ty + 8 * i;
        float q = ((w0[d] + w1[d]) + w2[d]) / 3.0f;
        size_t off = (size_t)b * DD * TT + (size_t)d * TT + t0 + tx;
        float xv = x[off];
        out[OUT_Q_OFF + off] = q;
        float df = q - xv;
        lsum += df * df;
    }
    #pragma unroll
    for (int off = 16; off; off >>= 1)
        lsum += __shfl_down_sync(0xffffffffu, lsum, off);
    if (tx == 0) red[ty] = (double)lsum;
    __syncthreads();
    if (tx == 0 && ty == 0) {
        double s = 0.0;
        #pragma unroll
        for (int i = 0; i < 8; i++) s += red[i];
        atomicAdd(&g_loss_sum, s);
    }
}

// ---------------------------------------------------------------------------
__global__ void k_final(float* __restrict__ out) {
    __shared__ float red[256];
    int tid = threadIdx.x;
    float local = 0.f;
    for (int k = tid; k < KK; k += 256) {
        float p = (float)g_counts[k] / 16384.0f;
        local += p * logf(p + 1e-10f);
    }
    red[tid] = local;
    __syncthreads();
    #pragma unroll
    for (int s = 128; s; s >>= 1) {
        if (tid < s) red[tid] += red[tid + s];
        __syncthreads();
    }
    if (tid == 0) {
        out[OUT_PERP_OFF] = expf(-red[0]);
        float m = (float)(g_loss_sum / (double)((size_t)NN * DD));
        out[0] = m + 0.25f * m;
    }
}

// ---------------------------------------------------------------------------
extern "C" void kernel_launch(void* const* d_in, const int* in_sizes, int n_in,
                              void* d_out, int out_size) {
    const float* x = (const float*)d_in[0];
    const float* W = (const float*)d_in[1];
    if (n_in >= 2 && in_sizes[0] == KK * DD && in_sizes[1] == BB * DD * TT) {
        const float* tmp = x; x = W; W = tmp;
    }
    float* out = (float*)d_out;
    (void)out_size;

    cudaFuncSetAttribute(k_gemm, cudaFuncAttributeMaxDynamicSharedMemorySize,
                         SMEM_TOTAL);

    // k_gemm stays at launch index 3 (ncu profiles launch #3).
    k_prep   <<<320, 256>>>(x, W);
    k_split_w<<<(KK * DD) / 256, 256>>>(W);       // also zeroes counts/loss
    k_split_x<<<dim3(16, 8, 64), dim3(32, 8)>>>(x);
    k_gemm   <<<dim3(KK / BN, NN / BM), 256, SMEM_TOTAL>>>();
    k_merge  <<<64, 256>>>();
    k_rescore<<<2048, 256>>>(W, out);
    k_out    <<<dim3(16, 8, 64), dim3(32, 8)>>>(x, W, out);
    k_final  <<<1, 256>>>(out);
}